// round 10
// baseline (speedup 1.0000x reference)
#include <cuda_runtime.h>

// PytorchLUTFakeQuant: t = clip(x*64, -128, 127); nearest of 16 sorted
// INTEGER centers (tie -> lower index); out = center / 64.
//
// 511-entry shared LUT indexed by ceil(clip(x*128, -256, 254)) + 256.
// (ceil-count identity reproduces argmin lower-index tie-break exactly;
// verified rel_err = 0.)
//
// Round 10: stall-overlap round. R9 showed the kernel is stall-bound
// (wall==ncu, issue 48%, occ 56%): front-batched loads make whole blocks
// stall in lockstep. Fix:
//  - depth-1 software pipeline: LDG.256 of chunk k+1 issues under the
//    compute+store of chunk k -> every warp always has a load in flight.
//  - live regs drop 32 floats -> ~24, so launch_bounds(128,16) doubles
//    resident blocks to 16/SM (2048 thr = 100% theoretical occupancy).
// Kept from R9: v8.b32 ld/st, L2::evict_last on x, discard on out.

static constexpr int NC = 16;
static constexpr int LUT_SIZE = 512;
static constexpr int BLOCK = 128;
static constexpr int V8 = 4;                  // float8 per thread = 32 floats

struct float8 { float4 a, b; };

__device__ __forceinline__ float8 ldg_el_256(const float8* p) {
    unsigned r0, r1, r2, r3, r4, r5, r6, r7;
    asm("ld.global.nc.L2::evict_last.v8.b32 {%0,%1,%2,%3,%4,%5,%6,%7}, [%8];"
        : "=r"(r0), "=r"(r1), "=r"(r2), "=r"(r3),
          "=r"(r4), "=r"(r5), "=r"(r6), "=r"(r7)
        : "l"(p));
    float8 v;
    v.a.x = __uint_as_float(r0); v.a.y = __uint_as_float(r1);
    v.a.z = __uint_as_float(r2); v.a.w = __uint_as_float(r3);
    v.b.x = __uint_as_float(r4); v.b.y = __uint_as_float(r5);
    v.b.z = __uint_as_float(r6); v.b.w = __uint_as_float(r7);
    return v;
}

__device__ __forceinline__ void stg_256(float8* p, float4 a, float4 b) {
    asm volatile("st.global.v8.b32 [%0], {%1,%2,%3,%4,%5,%6,%7,%8};"
                 :: "l"(p),
                    "r"(__float_as_uint(a.x)), "r"(__float_as_uint(a.y)),
                    "r"(__float_as_uint(a.z)), "r"(__float_as_uint(a.w)),
                    "r"(__float_as_uint(b.x)), "r"(__float_as_uint(b.y)),
                    "r"(__float_as_uint(b.z)), "r"(__float_as_uint(b.w))
                 : "memory");
}

__global__ void __launch_bounds__(BLOCK, 16)
lut_fakequant_kernel(const float8* __restrict__ x,
                     const float* __restrict__ centers,
                     float8* __restrict__ out) {
    __shared__ float lut[LUT_SIZE];

    // ---- Build LUT: lut[k] = cv[ #{ m_i <= k-257 } ] / 64 ----
    float cv[NC];
#pragma unroll
    for (int i = 0; i < NC; i++) cv[i] = __ldg(&centers[i]);
    float m[NC - 1];
#pragma unroll
    for (int i = 0; i < NC - 1; i++) m[i] = cv[i] + cv[i + 1];  // integer, exact

#pragma unroll
    for (int e = 0; e < LUT_SIZE / BLOCK; e++) {
        int k = threadIdx.x + e * BLOCK;
        float idxval = (float)(k - 257);
        int count = 0;
#pragma unroll
        for (int i = 0; i < NC - 1; i++) count += (m[i] <= idxval);
        lut[k] = cv[count] * 0.015625f;       // 1/64, exact
    }

    int base8 = blockIdx.x * (BLOCK * V8) + threadIdx.x;

    // Prologue load (chunk 0) issues before the barrier.
    float8 cur = ldg_el_256(&x[base8]);

    // ---- Discard this block's output lines (skip their HBM writeback) ----
    // Block chunk = BLOCK*V8 float8 = 16KB = 128 lines; one per thread.
    {
        char* line = (char*)(out + blockIdx.x * (BLOCK * V8)) +
                     threadIdx.x * 128;
        asm volatile("discard.global.L2 [%0], 128;" :: "l"(line) : "memory");
    }
    // Barrier orders LUT build + all discards before any store to the chunk.
    __syncthreads();

    const float* lutc = lut + 256;            // +256 folds into LDS imm offset

    // ---- Depth-1 pipelined main loop: load k+1 under compute of k ----
#pragma unroll
    for (int k = 0; k < V8; k++) {
        float8 nxt;
        if (k + 1 < V8)
            nxt = ldg_el_256(&x[base8 + (k + 1) * BLOCK]);

        float4 ra, rb;
        // FMUL, FMNMX, FMNMX, F2I.RU, LDS. Clamp [-256,254] exact:
        // spec clips t at -128 -> u >= -256 -> index 0 is correct floor.
#define QUANT_ONE(IN, OUT)                                              \
        do {                                                            \
            float u = fminf(fmaxf((IN) * 128.0f, -256.0f), 254.0f);     \
            (OUT) = lutc[__float2int_ru(u)];                            \
        } while (0)
        QUANT_ONE(cur.a.x, ra.x); QUANT_ONE(cur.a.y, ra.y);
        QUANT_ONE(cur.a.z, ra.z); QUANT_ONE(cur.a.w, ra.w);
        QUANT_ONE(cur.b.x, rb.x); QUANT_ONE(cur.b.y, rb.y);
        QUANT_ONE(cur.b.z, rb.z); QUANT_ONE(cur.b.w, rb.w);
#undef QUANT_ONE
        stg_256(&out[base8 + k * BLOCK], ra, rb);

        cur = nxt;
    }
}

// Generic tail kernel (unused for this shape; kept for safety).
__global__ void lut_fakequant_tail(const float4* __restrict__ x,
                                   const float* __restrict__ centers,
                                   float4* __restrict__ out,
                                   int start4, int n4) {
    __shared__ float lut[LUT_SIZE];
    if (threadIdx.x < LUT_SIZE) {
        int k = threadIdx.x;
        float idxval = (float)(k - 257);
        int count = 0;
        for (int i = 0; i < NC - 1; i++)
            count += (__ldg(&centers[i]) + __ldg(&centers[i + 1]) <= idxval);
        lut[k] = __ldg(&centers[count]) * 0.015625f;
    }
    __syncthreads();
    int i = start4 + blockIdx.x * blockDim.x + threadIdx.x;
    if (i >= n4) return;
    const float* lutc = lut + 256;
    float4 v = x[i], r;
#define QUANT_ONE(IN, OUT)                                              \
    do {                                                                \
        float u = fminf(fmaxf((IN) * 128.0f, -256.0f), 254.0f);         \
        (OUT) = lutc[__float2int_ru(u)];                                \
    } while (0)
    QUANT_ONE(v.x, r.x); QUANT_ONE(v.y, r.y);
    QUANT_ONE(v.z, r.z); QUANT_ONE(v.w, r.w);
#undef QUANT_ONE
    out[i] = r;
}

extern "C" void kernel_launch(void* const* d_in, const int* in_sizes, int n_in,
                              void* d_out, int out_size) {
    const float* x = (const float*)d_in[0];
    const float* centers = (const float*)d_in[1];
    if (n_in >= 2 && in_sizes[0] == NC && in_sizes[1] != NC) {
        x = (const float*)d_in[1];
        centers = (const float*)d_in[0];
    }

    int n8 = out_size / 8;                    // 1,605,632 float8 (exact)
    int per_block8 = BLOCK * V8;              // 512 float8 per block
    int main_blocks = n8 / per_block8;        // 3136 exact for this shape

    if (main_blocks > 0)
        lut_fakequant_kernel<<<main_blocks, BLOCK>>>(
            (const float8*)x, centers, (float8*)d_out);

    int done4 = main_blocks * per_block8 * 2;
    int n4 = out_size / 4;
    int rem4 = n4 - done4;
    if (rem4 > 0)
        lut_fakequant_tail<<<(rem4 + 511) / 512, 512>>>(
            (const float4*)x, centers, (float4*)d_out, done4, n4);
}

// round 11
// speedup vs baseline: 1.9123x; 1.9123x over previous
#include <cuda_runtime.h>

// PytorchLUTFakeQuant: t = clip(x*64, -128, 127); nearest of 16 sorted
// INTEGER centers (tie -> lower index); out = center / 64.
//
// 511-entry shared LUT indexed by ceil(clip(x*128, -256, 254)) + 256.
// (ceil-count identity reproduces argmin lower-index tie-break exactly;
// verified rel_err = 0.)
//
// Round 11: R9 inner shape kept EXACTLY (4x front-batched LDG.256 with
// L2::evict_last, STG.256, default store policy, discard-before-store,
// 40-reg budget). One change: CHUNKS=2 -> grid 1568 <= 148*12 resident
// blocks = SINGLE WAVE (no wave-2 underfill), and chunk 1's loads can
// overlap chunk 0's compute as registers free.
// (R10 lesson: never squeeze a pipeline into 32 regs — MLP collapses.)

static constexpr int NC = 16;
static constexpr int LUT_SIZE = 512;
static constexpr int BLOCK = 128;
static constexpr int V8 = 4;                  // float8 per chunk per thread
static constexpr int CHUNKS = 2;              // 2 chunks -> 32KB per block

struct float8 { float4 a, b; };

__device__ __forceinline__ float8 ldg_el_256(const float8* p) {
    unsigned r0, r1, r2, r3, r4, r5, r6, r7;
    asm("ld.global.nc.L2::evict_last.v8.b32 {%0,%1,%2,%3,%4,%5,%6,%7}, [%8];"
        : "=r"(r0), "=r"(r1), "=r"(r2), "=r"(r3),
          "=r"(r4), "=r"(r5), "=r"(r6), "=r"(r7)
        : "l"(p));
    float8 v;
    v.a.x = __uint_as_float(r0); v.a.y = __uint_as_float(r1);
    v.a.z = __uint_as_float(r2); v.a.w = __uint_as_float(r3);
    v.b.x = __uint_as_float(r4); v.b.y = __uint_as_float(r5);
    v.b.z = __uint_as_float(r6); v.b.w = __uint_as_float(r7);
    return v;
}

__device__ __forceinline__ void stg_256(float8* p, float4 a, float4 b) {
    asm volatile("st.global.v8.b32 [%0], {%1,%2,%3,%4,%5,%6,%7,%8};"
                 :: "l"(p),
                    "r"(__float_as_uint(a.x)), "r"(__float_as_uint(a.y)),
                    "r"(__float_as_uint(a.z)), "r"(__float_as_uint(a.w)),
                    "r"(__float_as_uint(b.x)), "r"(__float_as_uint(b.y)),
                    "r"(__float_as_uint(b.z)), "r"(__float_as_uint(b.w))
                 : "memory");
}

__global__ void __launch_bounds__(BLOCK, 12)
lut_fakequant_kernel(const float8* __restrict__ x,
                     const float* __restrict__ centers,
                     float8* __restrict__ out) {
    __shared__ float lut[LUT_SIZE];

    // ---- Build LUT: lut[k] = cv[ #{ m_i <= k-257 } ] / 64 ----
    float cv[NC];
#pragma unroll
    for (int i = 0; i < NC; i++) cv[i] = __ldg(&centers[i]);
    float m[NC - 1];
#pragma unroll
    for (int i = 0; i < NC - 1; i++) m[i] = cv[i] + cv[i + 1];  // integer, exact

#pragma unroll
    for (int e = 0; e < LUT_SIZE / BLOCK; e++) {
        int k = threadIdx.x + e * BLOCK;
        float idxval = (float)(k - 257);
        int count = 0;
#pragma unroll
        for (int i = 0; i < NC - 1; i++) count += (m[i] <= idxval);
        lut[k] = cv[count] * 0.015625f;       // 1/64, exact
    }

    // ---- Discard this block's output lines (skip their HBM writeback) ----
    // Block output = CHUNKS*V8*BLOCK float8 = 32KB = 256 lines; 2/thread.
    {
        char* base = (char*)(out + blockIdx.x * (BLOCK * V8 * CHUNKS));
        char* l0 = base + threadIdx.x * 128;
        char* l1 = base + (threadIdx.x + BLOCK) * 128;
        asm volatile("discard.global.L2 [%0], 128;" :: "l"(l0) : "memory");
        asm volatile("discard.global.L2 [%0], 128;" :: "l"(l1) : "memory");
    }
    // Barrier orders LUT build + all discards before any store to the chunk.
    __syncthreads();

    const float* lutc = lut + 256;            // +256 folds into LDS imm offset

#pragma unroll
    for (int c = 0; c < CHUNKS; c++) {
        int base8 = (blockIdx.x * CHUNKS + c) * (BLOCK * V8) + threadIdx.x;

        // ---- Front-batched 256-bit loads (4 x LDG.256 in flight) ----
        float8 v[V8];
#pragma unroll
        for (int k = 0; k < V8; k++)
            v[k] = ldg_el_256(&x[base8 + k * BLOCK]);

#pragma unroll
        for (int k = 0; k < V8; k++) {
            float4 ra, rb;
            // FMUL, FMNMX, FMNMX, F2I.RU, LDS. Clamp [-256,254] exact:
            // spec clips t at -128 -> u >= -256 -> index 0 is correct.
#define QUANT_ONE(IN, OUT)                                              \
            do {                                                        \
                float u = fminf(fmaxf((IN) * 128.0f, -256.0f), 254.0f); \
                (OUT) = lutc[__float2int_ru(u)];                        \
            } while (0)
            QUANT_ONE(v[k].a.x, ra.x); QUANT_ONE(v[k].a.y, ra.y);
            QUANT_ONE(v[k].a.z, ra.z); QUANT_ONE(v[k].a.w, ra.w);
            QUANT_ONE(v[k].b.x, rb.x); QUANT_ONE(v[k].b.y, rb.y);
            QUANT_ONE(v[k].b.z, rb.z); QUANT_ONE(v[k].b.w, rb.w);
#undef QUANT_ONE
            stg_256(&out[base8 + k * BLOCK], ra, rb);
        }
    }
}

// Generic tail kernel (unused for this shape; kept for safety).
__global__ void lut_fakequant_tail(const float4* __restrict__ x,
                                   const float* __restrict__ centers,
                                   float4* __restrict__ out,
                                   int start4, int n4) {
    __shared__ float lut[LUT_SIZE];
    if (threadIdx.x < LUT_SIZE) {
        int k = threadIdx.x;
        float idxval = (float)(k - 257);
        int count = 0;
        for (int i = 0; i < NC - 1; i++)
            count += (__ldg(&centers[i]) + __ldg(&centers[i + 1]) <= idxval);
        lut[k] = __ldg(&centers[count]) * 0.015625f;
    }
    __syncthreads();
    int i = start4 + blockIdx.x * blockDim.x + threadIdx.x;
    if (i >= n4) return;
    const float* lutc = lut + 256;
    float4 v = x[i], r;
#define QUANT_ONE(IN, OUT)                                              \
    do {                                                                \
        float u = fminf(fmaxf((IN) * 128.0f, -256.0f), 254.0f);         \
        (OUT) = lutc[__float2int_ru(u)];                                \
    } while (0)
    QUANT_ONE(v.x, r.x); QUANT_ONE(v.y, r.y);
    QUANT_ONE(v.z, r.z); QUANT_ONE(v.w, r.w);
#undef QUANT_ONE
    out[i] = r;
}

extern "C" void kernel_launch(void* const* d_in, const int* in_sizes, int n_in,
                              void* d_out, int out_size) {
    const float* x = (const float*)d_in[0];
    const float* centers = (const float*)d_in[1];
    if (n_in >= 2 && in_sizes[0] == NC && in_sizes[1] != NC) {
        x = (const float*)d_in[1];
        centers = (const float*)d_in[0];
    }

    int n8 = out_size / 8;                    // 1,605,632 float8 (exact)
    int per_block8 = BLOCK * V8 * CHUNKS;     // 1024 float8 per block
    int main_blocks = n8 / per_block8;        // 1568 exact for this shape

    if (main_blocks > 0)
        lut_fakequant_kernel<<<main_blocks, BLOCK>>>(
            (const float8*)x, centers, (float8*)d_out);

    int done4 = main_blocks * per_block8 * 2;
    int n4 = out_size / 4;
    int rem4 = n4 - done4;
    if (rem4 > 0)
        lut_fakequant_tail<<<(rem4 + 511) / 512, 512>>>(
            (const float4*)x, centers, (float4*)d_out, done4, n4);
}

// round 12
// speedup vs baseline: 1.9159x; 1.0019x over previous
#include <cuda_runtime.h>

// PytorchLUTFakeQuant: t = clip(x*64, -128, 127); nearest of 16 sorted
// INTEGER centers (tie -> lower index); out = center / 64.
//
// 511-entry shared LUT indexed by ceil(clip(x*128, -256, 254)) + 256.
// (ceil-count identity reproduces argmin lower-index tie-break exactly;
// verified rel_err = 0.)
//
// Round 12: prologue-cost round. Inner per-thread shape is EXACTLY R9's
// (4x front-batched LDG.256 w/ L2::evict_last, STG.256 default policy,
// discard-before-store, 40-reg budget). Geometry change only:
//   BLOCK=256, launch_bounds(256,6) -> same 48 warps/SM as R9, but
//   1568 blocks instead of 3136: half the barriers, half the total
//   LUT-build work (2 entries/thread), centers loaded as 4x float4.

static constexpr int NC = 16;
static constexpr int LUT_SIZE = 512;
static constexpr int BLOCK = 256;
static constexpr int V8 = 4;                  // float8 per thread = 32 floats

struct float8 { float4 a, b; };

__device__ __forceinline__ float8 ldg_el_256(const float8* p) {
    unsigned r0, r1, r2, r3, r4, r5, r6, r7;
    asm("ld.global.nc.L2::evict_last.v8.b32 {%0,%1,%2,%3,%4,%5,%6,%7}, [%8];"
        : "=r"(r0), "=r"(r1), "=r"(r2), "=r"(r3),
          "=r"(r4), "=r"(r5), "=r"(r6), "=r"(r7)
        : "l"(p));
    float8 v;
    v.a.x = __uint_as_float(r0); v.a.y = __uint_as_float(r1);
    v.a.z = __uint_as_float(r2); v.a.w = __uint_as_float(r3);
    v.b.x = __uint_as_float(r4); v.b.y = __uint_as_float(r5);
    v.b.z = __uint_as_float(r6); v.b.w = __uint_as_float(r7);
    return v;
}

__device__ __forceinline__ void stg_256(float8* p, float4 a, float4 b) {
    asm volatile("st.global.v8.b32 [%0], {%1,%2,%3,%4,%5,%6,%7,%8};"
                 :: "l"(p),
                    "r"(__float_as_uint(a.x)), "r"(__float_as_uint(a.y)),
                    "r"(__float_as_uint(a.z)), "r"(__float_as_uint(a.w)),
                    "r"(__float_as_uint(b.x)), "r"(__float_as_uint(b.y)),
                    "r"(__float_as_uint(b.z)), "r"(__float_as_uint(b.w))
                 : "memory");
}

__global__ void __launch_bounds__(BLOCK, 6)
lut_fakequant_kernel(const float8* __restrict__ x,
                     const float* __restrict__ centers,
                     float8* __restrict__ out) {
    __shared__ float lut[LUT_SIZE];

    // ---- Build LUT: lut[k] = cv[ #{ m_i <= k-257 } ] / 64 ----
    // Centers via 4 vector loads (broadcast across block, L1-resident).
    const float4* c4 = (const float4*)centers;
    float4 g0 = __ldg(c4 + 0), g1 = __ldg(c4 + 1),
           g2 = __ldg(c4 + 2), g3 = __ldg(c4 + 3);
    float cv[NC] = {g0.x, g0.y, g0.z, g0.w, g1.x, g1.y, g1.z, g1.w,
                    g2.x, g2.y, g2.z, g2.w, g3.x, g3.y, g3.z, g3.w};
    float m[NC - 1];
#pragma unroll
    for (int i = 0; i < NC - 1; i++) m[i] = cv[i] + cv[i + 1];  // integer, exact

#pragma unroll
    for (int e = 0; e < LUT_SIZE / BLOCK; e++) {               // 2 entries/thr
        int k = threadIdx.x + e * BLOCK;
        float idxval = (float)(k - 257);
        int count = 0;
#pragma unroll
        for (int i = 0; i < NC - 1; i++) count += (m[i] <= idxval);
        lut[k] = cv[count] * 0.015625f;       // 1/64, exact
    }

    int base8 = blockIdx.x * (BLOCK * V8) + threadIdx.x;

    // ---- Front-batched 256-bit loads (4 x LDG.256, 128B in flight) ----
    float8 v[V8];
#pragma unroll
    for (int k = 0; k < V8; k++)
        v[k] = ldg_el_256(&x[base8 + k * BLOCK]);

    // ---- Discard this block's output lines (skip their HBM writeback) ----
    // Block output = BLOCK*V8 float8 = 32KB = 256 lines; one per thread.
    {
        char* line = (char*)(out + blockIdx.x * (BLOCK * V8)) +
                     threadIdx.x * 128;
        asm volatile("discard.global.L2 [%0], 128;" :: "l"(line) : "memory");
    }
    // Barrier orders LUT build + all discards before any store to the chunk.
    __syncthreads();

    const float* lutc = lut + 256;            // +256 folds into LDS imm offset

#pragma unroll
    for (int k = 0; k < V8; k++) {
        float4 ra, rb;
        // FMUL, FMNMX, FMNMX, F2I.RU, LDS. Clamp [-256,254] exact:
        // spec clips t at -128 -> u >= -256 -> index 0 is correct floor.
#define QUANT_ONE(IN, OUT)                                              \
        do {                                                            \
            float u = fminf(fmaxf((IN) * 128.0f, -256.0f), 254.0f);     \
            (OUT) = lutc[__float2int_ru(u)];                            \
        } while (0)
        QUANT_ONE(v[k].a.x, ra.x); QUANT_ONE(v[k].a.y, ra.y);
        QUANT_ONE(v[k].a.z, ra.z); QUANT_ONE(v[k].a.w, ra.w);
        QUANT_ONE(v[k].b.x, rb.x); QUANT_ONE(v[k].b.y, rb.y);
        QUANT_ONE(v[k].b.z, rb.z); QUANT_ONE(v[k].b.w, rb.w);
#undef QUANT_ONE
        stg_256(&out[base8 + k * BLOCK], ra, rb);
    }
}

// Generic tail kernel (unused for this shape; kept for safety).
__global__ void lut_fakequant_tail(const float4* __restrict__ x,
                                   const float* __restrict__ centers,
                                   float4* __restrict__ out,
                                   int start4, int n4) {
    __shared__ float lut[LUT_SIZE];
    if (threadIdx.x < LUT_SIZE) {
        int k = threadIdx.x;
        float idxval = (float)(k - 257);
        int count = 0;
        for (int i = 0; i < NC - 1; i++)
            count += (__ldg(&centers[i]) + __ldg(&centers[i + 1]) <= idxval);
        lut[k] = __ldg(&centers[count]) * 0.015625f;
    }
    __syncthreads();
    int i = start4 + blockIdx.x * blockDim.x + threadIdx.x;
    if (i >= n4) return;
    const float* lutc = lut + 256;
    float4 v = x[i], r;
#define QUANT_ONE(IN, OUT)                                              \
    do {                                                                \
        float u = fminf(fmaxf((IN) * 128.0f, -256.0f), 254.0f);         \
        (OUT) = lutc[__float2int_ru(u)];                                \
    } while (0)
    QUANT_ONE(v.x, r.x); QUANT_ONE(v.y, r.y);
    QUANT_ONE(v.z, r.z); QUANT_ONE(v.w, r.w);
#undef QUANT_ONE
    out[i] = r;
}

extern "C" void kernel_launch(void* const* d_in, const int* in_sizes, int n_in,
                              void* d_out, int out_size) {
    const float* x = (const float*)d_in[0];
    const float* centers = (const float*)d_in[1];
    if (n_in >= 2 && in_sizes[0] == NC && in_sizes[1] != NC) {
        x = (const float*)d_in[1];
        centers = (const float*)d_in[0];
    }

    int n8 = out_size / 8;                    // 1,605,632 float8 (exact)
    int per_block8 = BLOCK * V8;              // 1024 float8 per block
    int main_blocks = n8 / per_block8;        // 1568 exact for this shape

    if (main_blocks > 0)
        lut_fakequant_kernel<<<main_blocks, BLOCK>>>(
            (const float8*)x, centers, (float8*)d_out);

    int done4 = main_blocks * per_block8 * 2;
    int n4 = out_size / 4;
    int rem4 = n4 - done4;
    if (rem4 > 0)
        lut_fakequant_tail<<<(rem4 + 511) / 512, 512>>>(
            (const float4*)x, centers, (float4*)d_out, done4, n4);
}